// round 10
// baseline (speedup 1.0000x reference)
#include <cuda_runtime.h>
#include <cstdint>

#define NMAX 100000
#define EMAX 1600000
#define FIN  128
#define FOUT 40
#define SCAN_BLK 1024

typedef unsigned long long ull;

// Scratch (static __device__ — no allocations allowed)
__device__ int   g_is64;
__device__ int   g_src32 [EMAX];
__device__ int   g_dst32 [EMAX];
__device__ int   g_csr   [EMAX];        // src ids grouped by dst
__device__ int   g_degi  [NMAX];
__device__ int   g_fill  [NMAX];
__device__ int   g_rowptr[NMAX + 1];
__device__ int   g_bsum  [(NMAX + SCAN_BLK - 1) / SCAN_BLK];
__device__ int   g_boff  [(NMAX + SCAN_BLK - 1) / SCAN_BLK];
__device__ float g_dinv[NMAX];
__device__ float g_h   [(size_t)NMAX * FIN];   // x @ W1 (UNscaled)
__device__ float g_a1  [(size_t)NMAX * FIN];   // relu(layer-1 out)
__device__ float g_h2  [(size_t)NMAX * FOUT];  // dinv * (a1 @ W2)

// ---------------------------------------------------------------------------
// preproc
// ---------------------------------------------------------------------------
__global__ void k_zero_cnt(int n) {
    int i = blockIdx.x * blockDim.x + threadIdx.x;
    if (i < n) { g_degi[i] = 0; g_fill[i] = 0; }
    if (i == 0) g_is64 = 1;
}

__global__ void k_detect(const long long* __restrict__ ei, int n, int count) {
    int i = blockIdx.x * blockDim.x + threadIdx.x;
    if (i < count) {
        long long v = ei[i];
        if (v < 0 || v >= (long long)n) atomicAnd(&g_is64, 0);
    }
}

__global__ void k_convert_hist(const void* __restrict__ ei, int E) {
    int e = blockIdx.x * blockDim.x + threadIdx.x;
    if (e >= E) return;
    int s, d;
    if (g_is64) {
        const long long* p = (const long long*)ei;
        s = (int)p[e];
        d = (int)p[E + e];
    } else {
        const int* p = (const int*)ei;
        s = p[e];
        d = p[E + e];
    }
    g_src32[e] = s;
    g_dst32[e] = d;
    atomicAdd(&g_degi[d], 1);
}

__global__ void k_scanA(int n) {
    __shared__ int sh[SCAN_BLK];
    int tid = threadIdx.x;
    int i = blockIdx.x * SCAN_BLK + tid;
    int v = (i < n) ? g_degi[i] : 0;
    if (i < n) g_dinv[i] = rsqrtf((float)v + 1.0f);  // +1 = self loop
    sh[tid] = v;
    __syncthreads();
    for (int off = 1; off < SCAN_BLK; off <<= 1) {
        int t = (tid >= off) ? sh[tid - off] : 0;
        __syncthreads();
        sh[tid] += t;
        __syncthreads();
    }
    if (i < n) g_rowptr[i] = sh[tid] - v;  // exclusive within block
    if (tid == SCAN_BLK - 1) g_bsum[blockIdx.x] = sh[tid];
}

__global__ void k_scanB(int nblocks, int n, int E) {
    __shared__ int sh[256];
    int tid = threadIdx.x;
    int carry = 0;
    for (int base = 0; base < nblocks; base += 256) {
        int i = base + tid;
        int v = (i < nblocks) ? g_bsum[i] : 0;
        sh[tid] = v;
        __syncthreads();
        for (int off = 1; off < 256; off <<= 1) {
            int t = (tid >= off) ? sh[tid - off] : 0;
            __syncthreads();
            sh[tid] += t;
            __syncthreads();
        }
        if (i < nblocks) g_boff[i] = carry + sh[tid] - v;
        __syncthreads();
        carry += sh[255];
        __syncthreads();
    }
    if (tid == 0) g_rowptr[n] = E;
}

__global__ void k_scanC(int n) {
    int i = blockIdx.x * blockDim.x + threadIdx.x;
    if (i < n) g_rowptr[i] += g_boff[i / SCAN_BLK];
}

__global__ void k_fill(int E) {
    int e = blockIdx.x * blockDim.x + threadIdx.x;
    if (e >= E) return;
    int d = g_dst32[e];
    int pos = g_rowptr[d] + atomicAdd(&g_fill[d], 1);
    g_csr[pos] = g_src32[e];
}

// ---------------------------------------------------------------------------
// GEMM1: h = x @ W1 (unscaled), packed f32x2 FMA.
// block = 512 threads, tile = 128 rows x 128 cols, K chunked by 32.
// thread: cg = t&15 -> cols cg*8..+7 ; rg = t>>4 -> rows rg*4..+3.
// R8 dataflow, doubled occupancy (acc = 16 ull = 32 regs).
// ---------------------------------------------------------------------------
__global__ void __launch_bounds__(512, 2)
k_gemm1(const float* __restrict__ x, const float* __restrict__ W, int n) {
    const int KC  = 32;
    const int KC2 = KC / 2;
    __shared__ float      Ws [KC * FIN];     // 16 KB
    __shared__ ulonglong2 Xs2[128 * KC2];    // 32 KB, [row][kk2]

    int t    = threadIdx.x;
    int cg   = t & 15;         // col group: cols cg*8 .. cg*8+7
    int rg   = t >> 4;         // row group: rows rg*4 .. rg*4+3
    int row0 = blockIdx.x * 128;

    ull acc[4][4];
#pragma unroll
    for (int r = 0; r < 4; r++)
#pragma unroll
        for (int c = 0; c < 4; c++) acc[r][c] = 0ull;

    for (int kc = 0; kc < FIN; kc += KC) {
        // stage W rows kc..kc+KC (contiguous 32x128 floats)
        for (int i = t; i < KC * FIN / 4; i += 512)
            ((float4*)Ws)[i] = ((const float4*)(W + (size_t)kc * FIN))[i];
        // stage x tile: [row][kk2], cell = {dup(v_2k), dup(v_2k+1)}
        for (int i = t; i < 128 * KC2; i += 512) {
            int r  = i >> 4;
            int k2 = i & 15;
            int gr = row0 + r;
            float2 v = make_float2(0.f, 0.f);
            if (gr < n) v = *(const float2*)(x + (size_t)gr * FIN + kc + k2 * 2);
            ulonglong2 e;
            *(float2*)&e.x = make_float2(v.x, v.x);
            *(float2*)&e.y = make_float2(v.y, v.y);
            Xs2[i] = e;
        }
        __syncthreads();

#pragma unroll 4
        for (int kk2 = 0; kk2 < KC2; kk2++) {
            ulonglong2 xx[4];
#pragma unroll
            for (int r = 0; r < 4; r++)
                xx[r] = Xs2[(rg * 4 + r) * KC2 + kk2];
#pragma unroll
            for (int half = 0; half < 2; half++) {
                int kk = 2 * kk2 + half;
                const ulonglong2* wp = (const ulonglong2*)(Ws + kk * FIN + cg * 8);
                ulonglong2 wa = wp[0];
                ulonglong2 wb = wp[1];
#pragma unroll
                for (int r = 0; r < 4; r++) {
                    ull xv = half ? xx[r].y : xx[r].x;
                    asm("fma.rn.f32x2 %0, %1, %2, %0;" : "+l"(acc[r][0]) : "l"(xv), "l"(wa.x));
                    asm("fma.rn.f32x2 %0, %1, %2, %0;" : "+l"(acc[r][1]) : "l"(xv), "l"(wa.y));
                    asm("fma.rn.f32x2 %0, %1, %2, %0;" : "+l"(acc[r][2]) : "l"(xv), "l"(wb.x));
                    asm("fma.rn.f32x2 %0, %1, %2, %0;" : "+l"(acc[r][3]) : "l"(xv), "l"(wb.y));
                }
            }
        }
        __syncthreads();
    }

#pragma unroll
    for (int r = 0; r < 4; r++) {
        int gr = row0 + rg * 4 + r;
        if (gr < n) {
            float2 p0 = *(float2*)&acc[r][0];
            float2 p1 = *(float2*)&acc[r][1];
            float2 p2 = *(float2*)&acc[r][2];
            float2 p3 = *(float2*)&acc[r][3];
            float4* op = (float4*)(g_h + (size_t)gr * FIN + cg * 8);
            op[0] = make_float4(p0.x, p0.y, p1.x, p1.y);
            op[1] = make_float4(p2.x, p2.y, p3.x, p3.y);
        }
    }
}

// ---------------------------------------------------------------------------
// agg1 (pull): a1[d] = relu( di * (sum_s dinv[s]*h[s] + di*h[d]) + b1 )
// warp per node, lane holds float4 (4 cols), 4-way unrolled gather
// ---------------------------------------------------------------------------
__global__ void k_agg1(const float* __restrict__ b1, int n) {
    int node = blockIdx.x * 8 + (threadIdx.x >> 5);
    int lane = threadIdx.x & 31;
    if (node >= n) return;

    float di = g_dinv[node];
    float4 acc = ((const float4*)(g_h + (size_t)node * FIN))[lane];
    acc.x *= di; acc.y *= di; acc.z *= di; acc.w *= di;

    int beg = g_rowptr[node], end = g_rowptr[node + 1];
    int k = beg;
    for (; k + 3 < end; k += 4) {
        int s0 = g_csr[k],     s1 = g_csr[k + 1];
        int s2 = g_csr[k + 2], s3 = g_csr[k + 3];
        float w0 = g_dinv[s0], w1 = g_dinv[s1];
        float w2 = g_dinv[s2], w3 = g_dinv[s3];
        float4 v0 = ((const float4*)(g_h + (size_t)s0 * FIN))[lane];
        float4 v1 = ((const float4*)(g_h + (size_t)s1 * FIN))[lane];
        float4 v2 = ((const float4*)(g_h + (size_t)s2 * FIN))[lane];
        float4 v3 = ((const float4*)(g_h + (size_t)s3 * FIN))[lane];
        acc.x = fmaf(v0.x, w0, fmaf(v1.x, w1, fmaf(v2.x, w2, fmaf(v3.x, w3, acc.x))));
        acc.y = fmaf(v0.y, w0, fmaf(v1.y, w1, fmaf(v2.y, w2, fmaf(v3.y, w3, acc.y))));
        acc.z = fmaf(v0.z, w0, fmaf(v1.z, w1, fmaf(v2.z, w2, fmaf(v3.z, w3, acc.z))));
        acc.w = fmaf(v0.w, w0, fmaf(v1.w, w1, fmaf(v2.w, w2, fmaf(v3.w, w3, acc.w))));
    }
    for (; k < end; k++) {
        int s = g_csr[k];
        float w = g_dinv[s];
        float4 v = ((const float4*)(g_h + (size_t)s * FIN))[lane];
        acc.x = fmaf(v.x, w, acc.x);
        acc.y = fmaf(v.y, w, acc.y);
        acc.z = fmaf(v.z, w, acc.z);
        acc.w = fmaf(v.w, w, acc.w);
    }

    float4 bb = ((const float4*)b1)[lane];
    float4 z;
    z.x = fmaxf(fmaf(acc.x, di, bb.x), 0.f);
    z.y = fmaxf(fmaf(acc.y, di, bb.y), 0.f);
    z.z = fmaxf(fmaf(acc.z, di, bb.z), 0.f);
    z.w = fmaxf(fmaf(acc.w, di, bb.w), 0.f);
    ((float4*)(g_a1 + (size_t)node * FIN))[lane] = z;
}

// ---------------------------------------------------------------------------
// GEMM2: h2 = dinv * (a1 @ W2)   (N x 128 @ 128 x 40), register-tiled
// ---------------------------------------------------------------------------
__global__ void k_gemm2(const float* __restrict__ W2, int n) {
    const int KC = 32;
    __shared__ float W2s[FIN * FOUT];        // 20 KB
    __shared__ float As[128 * 36];           // 18 KB (pad 36)

    int t    = threadIdx.x;
    int r    = t >> 1;
    int half = t & 1;
    int row0 = blockIdx.x * 128;

    for (int i = t; i < FIN * FOUT / 4; i += 256)
        ((float4*)W2s)[i] = ((const float4*)W2)[i];

    float4 acc[5];
#pragma unroll
    for (int j = 0; j < 5; j++) acc[j] = make_float4(0.f, 0.f, 0.f, 0.f);

    for (int kc = 0; kc < FIN; kc += KC) {
        for (int i = t; i < 128 * (KC / 4); i += 256) {
            int rr = i >> 3;
            int k4 = i & 7;
            int gr = row0 + rr;
            float4 v = make_float4(0.f, 0.f, 0.f, 0.f);
            if (gr < n) v = ((const float4*)(g_a1 + (size_t)gr * FIN + kc))[k4];
            *(float4*)&As[rr * 36 + k4 * 4] = v;
        }
        __syncthreads();

#pragma unroll 4
        for (int kk = 0; kk < KC; kk++) {
            float av = As[r * 36 + kk];
            const float4* wp = (const float4*)(W2s + (kc + kk) * FOUT + half * 20);
            float4 w0 = wp[0];
            float4 w1 = wp[1];
            float4 w2 = wp[2];
            float4 w3 = wp[3];
            float4 w4 = wp[4];
            acc[0].x = fmaf(av, w0.x, acc[0].x); acc[0].y = fmaf(av, w0.y, acc[0].y);
            acc[0].z = fmaf(av, w0.z, acc[0].z); acc[0].w = fmaf(av, w0.w, acc[0].w);
            acc[1].x = fmaf(av, w1.x, acc[1].x); acc[1].y = fmaf(av, w1.y, acc[1].y);
            acc[1].z = fmaf(av, w1.z, acc[1].z); acc[1].w = fmaf(av, w1.w, acc[1].w);
            acc[2].x = fmaf(av, w2.x, acc[2].x); acc[2].y = fmaf(av, w2.y, acc[2].y);
            acc[2].z = fmaf(av, w2.z, acc[2].z); acc[2].w = fmaf(av, w2.w, acc[2].w);
            acc[3].x = fmaf(av, w3.x, acc[3].x); acc[3].y = fmaf(av, w3.y, acc[3].y);
            acc[3].z = fmaf(av, w3.z, acc[3].z); acc[3].w = fmaf(av, w3.w, acc[3].w);
            acc[4].x = fmaf(av, w4.x, acc[4].x); acc[4].y = fmaf(av, w4.y, acc[4].y);
            acc[4].z = fmaf(av, w4.z, acc[4].z); acc[4].w = fmaf(av, w4.w, acc[4].w);
        }
        __syncthreads();
    }

    int gr = row0 + r;
    if (gr < n) {
        float di = g_dinv[gr];
        float4* op = (float4*)(g_h2 + (size_t)gr * FOUT + half * 20);
#pragma unroll
        for (int j = 0; j < 5; j++) {
            float4 o = acc[j];
            o.x *= di; o.y *= di; o.z *= di; o.w *= di;
            op[j] = o;
        }
    }
}

// ---------------------------------------------------------------------------
// agg2 (pull): out[d] = di * (sum h2[s] + h2[d]) + b2    [h2 pre-scaled]
// ---------------------------------------------------------------------------
__global__ void k_agg2(float* __restrict__ out, const float* __restrict__ b2,
                       int n) {
    int node = blockIdx.x * 8 + (threadIdx.x >> 5);
    int lane = threadIdx.x & 31;
    if (node >= n) return;

    float di = g_dinv[node];
    const float* hp0 = g_h2 + (size_t)node * FOUT;
    float a0 = hp0[lane];
    float a1 = (lane < 8) ? hp0[32 + lane] : 0.f;

    int beg = g_rowptr[node], end = g_rowptr[node + 1];
    int k = beg;
    for (; k + 3 < end; k += 4) {
        const float* p0 = g_h2 + (size_t)g_csr[k]     * FOUT;
        const float* p1 = g_h2 + (size_t)g_csr[k + 1] * FOUT;
        const float* p2 = g_h2 + (size_t)g_csr[k + 2] * FOUT;
        const float* p3 = g_h2 + (size_t)g_csr[k + 3] * FOUT;
        a0 += (p0[lane] + p1[lane]) + (p2[lane] + p3[lane]);
        if (lane < 8)
            a1 += (p0[32 + lane] + p1[32 + lane]) + (p2[32 + lane] + p3[32 + lane]);
    }
    for (; k < end; k++) {
        const float* p = g_h2 + (size_t)g_csr[k] * FOUT;
        a0 += p[lane];
        if (lane < 8) a1 += p[32 + lane];
    }

    float* op = out + (size_t)node * FOUT;
    op[lane] = fmaf(a0, di, b2[lane]);
    if (lane < 8) op[32 + lane] = fmaf(a1, di, b2[32 + lane]);
}

// ---------------------------------------------------------------------------
extern "C" void kernel_launch(void* const* d_in, const int* in_sizes, int n_in,
                              void* d_out, int out_size) {
    const float* x   = (const float*)d_in[0];
    const void*  ei  = d_in[1];
    const float* W1  = (const float*)d_in[2];
    const float* b1  = (const float*)d_in[3];
    const float* W2  = (const float*)d_in[4];
    const float* b2  = (const float*)d_in[5];
    float*       out = (float*)d_out;

    int n = in_sizes[0] / FIN;
    if (n > NMAX) n = NMAX;
    int E = in_sizes[1] / 2;
    if (E > EMAX) E = EMAX;

    int detect_cnt = 2048;
    if (detect_cnt > E) detect_cnt = E;
    int nsb = (n + SCAN_BLK - 1) / SCAN_BLK;

    k_zero_cnt    <<<(n + 255) / 256, 256>>>(n);                 // 1 (also inits g_is64)
    k_detect      <<<(detect_cnt + 255) / 256, 256>>>((const long long*)ei, n, detect_cnt); // 2
    k_convert_hist<<<(E + 255) / 256, 256>>>(ei, E);             // 3
    k_gemm1       <<<(n + 127) / 128, 512>>>(x, W1, n);          // 4 <- profiled
    k_scanA       <<<nsb, SCAN_BLK>>>(n);                        // 5
    k_scanB       <<<1, 256>>>(nsb, n, E);                       // 6
    k_scanC       <<<(n + 255) / 256, 256>>>(n);                 // 7
    k_fill        <<<(E + 255) / 256, 256>>>(E);                 // 8
    k_agg1        <<<(n + 7) / 8, 256>>>(b1, n);                 // 9
    k_gemm2       <<<(n + 127) / 128, 256>>>(W2, n);             // 10
    k_agg2        <<<(n + 7) / 8, 256>>>(out, b2, n);            // 11
}

// round 11
// speedup vs baseline: 1.1962x; 1.1962x over previous
#include <cuda_runtime.h>
#include <cstdint>

#define NMAX 100000
#define EMAX 1600000
#define FIN  128
#define FOUT 40
#define SCAN_BLK 1024

typedef unsigned long long ull;

// Scratch (static __device__ — no allocations allowed)
__device__ int   g_is64;
__device__ int   g_src32 [EMAX];
__device__ int   g_dst32 [EMAX];
__device__ int   g_csr   [EMAX];        // src ids grouped by dst
__device__ int   g_degi  [NMAX];
__device__ int   g_fill  [NMAX];
__device__ int   g_rowptr[NMAX + 1];
__device__ int   g_bsum  [(NMAX + SCAN_BLK - 1) / SCAN_BLK];
__device__ int   g_boff  [(NMAX + SCAN_BLK - 1) / SCAN_BLK];
__device__ float g_dinv[NMAX];
__device__ float g_h   [(size_t)NMAX * FIN];   // x @ W1 (UNscaled)
__device__ float g_a1  [(size_t)NMAX * FIN];   // relu(layer-1 out)
__device__ float g_h2  [(size_t)NMAX * FOUT];  // dinv * (a1 @ W2)

// ---------------------------------------------------------------------------
// preproc
// ---------------------------------------------------------------------------
__global__ void k_zero_cnt(int n) {
    int i = blockIdx.x * blockDim.x + threadIdx.x;
    if (i < n) { g_degi[i] = 0; g_fill[i] = 0; }
    if (i == 0) g_is64 = 1;
}

__global__ void k_detect(const long long* __restrict__ ei, int n, int count) {
    int i = blockIdx.x * blockDim.x + threadIdx.x;
    if (i < count) {
        long long v = ei[i];
        if (v < 0 || v >= (long long)n) atomicAnd(&g_is64, 0);
    }
}

__global__ void k_convert_hist(const void* __restrict__ ei, int E) {
    int e = blockIdx.x * blockDim.x + threadIdx.x;
    if (e >= E) return;
    int s, d;
    if (g_is64) {
        const long long* p = (const long long*)ei;
        s = (int)p[e];
        d = (int)p[E + e];
    } else {
        const int* p = (const int*)ei;
        s = p[e];
        d = p[E + e];
    }
    g_src32[e] = s;
    g_dst32[e] = d;
    atomicAdd(&g_degi[d], 1);
}

__global__ void k_scanA(int n) {
    __shared__ int sh[SCAN_BLK];
    int tid = threadIdx.x;
    int i = blockIdx.x * SCAN_BLK + tid;
    int v = (i < n) ? g_degi[i] : 0;
    if (i < n) g_dinv[i] = rsqrtf((float)v + 1.0f);  // +1 = self loop
    sh[tid] = v;
    __syncthreads();
    for (int off = 1; off < SCAN_BLK; off <<= 1) {
        int t = (tid >= off) ? sh[tid - off] : 0;
        __syncthreads();
        sh[tid] += t;
        __syncthreads();
    }
    if (i < n) g_rowptr[i] = sh[tid] - v;  // exclusive within block
    if (tid == SCAN_BLK - 1) g_bsum[blockIdx.x] = sh[tid];
}

__global__ void k_scanB(int nblocks, int n, int E) {
    __shared__ int sh[256];
    int tid = threadIdx.x;
    int carry = 0;
    for (int base = 0; base < nblocks; base += 256) {
        int i = base + tid;
        int v = (i < nblocks) ? g_bsum[i] : 0;
        sh[tid] = v;
        __syncthreads();
        for (int off = 1; off < 256; off <<= 1) {
            int t = (tid >= off) ? sh[tid - off] : 0;
            __syncthreads();
            sh[tid] += t;
            __syncthreads();
        }
        if (i < nblocks) g_boff[i] = carry + sh[tid] - v;
        __syncthreads();
        carry += sh[255];
        __syncthreads();
    }
    if (tid == 0) g_rowptr[n] = E;
}

__global__ void k_scanC(int n) {
    int i = blockIdx.x * blockDim.x + threadIdx.x;
    if (i < n) g_rowptr[i] += g_boff[i / SCAN_BLK];
}

__global__ void k_fill(int E) {
    int e = blockIdx.x * blockDim.x + threadIdx.x;
    if (e >= E) return;
    int d = g_dst32[e];
    int pos = g_rowptr[d] + atomicAdd(&g_fill[d], 1);
    g_csr[pos] = g_src32[e];
}

// ---------------------------------------------------------------------------
// GEMM1: h = x @ W1 (unscaled), packed f32x2 FMA, conflict-free smem.
// block = 256 threads, tile = 128 rows x 128 cols, K chunked by 32.
// thread: cg = t&15 -> cols cg*8..+7 ; rg = t>>4 -> rows rg*8..+7.
// Ws cells [kk][half][cg]: 16 consecutive 16B cells per half -> 2 wf/load.
// Xs cells [row][kk2 ^ ((rg&1)<<2)]: half-warp pair lands in disjoint
// bank groups -> 1 wf/load.
// ---------------------------------------------------------------------------
__global__ void __launch_bounds__(256, 2)
k_gemm1(const float* __restrict__ x, const float* __restrict__ W, int n) {
    const int KC  = 32;
    const int KC2 = KC / 2;
    __shared__ float      Ws [KC * FIN];     // 16 KB, [kk][half][cg] 16B cells
    __shared__ ulonglong2 Xs2[128 * KC2];    // 32 KB, [row][kk2 swizzled]

    int t    = threadIdx.x;
    int cg   = t & 15;         // col group: cols cg*8 .. cg*8+7
    int rg   = t >> 4;         // row group: rows rg*8 .. rg*8+7
    int row0 = blockIdx.x * 128;
    int sx   = (rg & 1) << 2;  // Xs bank swizzle for this thread

    ull acc[8][4];
#pragma unroll
    for (int r = 0; r < 8; r++)
#pragma unroll
        for (int c = 0; c < 4; c++) acc[r][c] = 0ull;

    for (int kc = 0; kc < FIN; kc += KC) {
        // stage W: float4 f covers row kk=f>>5, cols (f&31)*4..+3.
        // cell index (float4 units) = kk*32 + half*16 + cg
        for (int f = t; f < KC * FIN / 4; f += 256) {
            float4 v = ((const float4*)(W + (size_t)kc * FIN))[f];
            int kk = f >> 5;
            int c4 = f & 31;
            ((float4*)Ws)[kk * 32 + (c4 & 1) * 16 + (c4 >> 1)] = v;
        }
        // stage x: [row][kk2^swz] cells = {dup(v_2k), dup(v_2k+1)}
        for (int i = t; i < 128 * KC2; i += 256) {
            int r  = i >> 4;
            int k2 = i & 15;
            int gr = row0 + r;
            float2 v = make_float2(0.f, 0.f);
            if (gr < n) v = *(const float2*)(x + (size_t)gr * FIN + kc + k2 * 2);
            ulonglong2 e;
            *(float2*)&e.x = make_float2(v.x, v.x);
            *(float2*)&e.y = make_float2(v.y, v.y);
            Xs2[r * KC2 + (k2 ^ (((r >> 3) & 1) << 2))] = e;
        }
        __syncthreads();

#pragma unroll 4
        for (int kk2 = 0; kk2 < KC2; kk2++) {
            int kidx = kk2 ^ sx;
#pragma unroll
            for (int half = 0; half < 2; half++) {
                int kk = 2 * kk2 + half;
                ulonglong2 wa = ((const ulonglong2*)Ws)[kk * 32 + cg];       // cols +0..3
                ulonglong2 wb = ((const ulonglong2*)Ws)[kk * 32 + 16 + cg];  // cols +4..7
#pragma unroll
                for (int r = 0; r < 8; r++) {
                    ulonglong2 xx = Xs2[(rg * 8 + r) * KC2 + kidx];
                    ull xv = half ? xx.y : xx.x;
                    asm("fma.rn.f32x2 %0, %1, %2, %0;" : "+l"(acc[r][0]) : "l"(xv), "l"(wa.x));
                    asm("fma.rn.f32x2 %0, %1, %2, %0;" : "+l"(acc[r][1]) : "l"(xv), "l"(wa.y));
                    asm("fma.rn.f32x2 %0, %1, %2, %0;" : "+l"(acc[r][2]) : "l"(xv), "l"(wb.x));
                    asm("fma.rn.f32x2 %0, %1, %2, %0;" : "+l"(acc[r][3]) : "l"(xv), "l"(wb.y));
                }
            }
        }
        __syncthreads();
    }

#pragma unroll
    for (int r = 0; r < 8; r++) {
        int gr = row0 + rg * 8 + r;
        if (gr < n) {
            float2 p0 = *(float2*)&acc[r][0];
            float2 p1 = *(float2*)&acc[r][1];
            float2 p2 = *(float2*)&acc[r][2];
            float2 p3 = *(float2*)&acc[r][3];
            float4* op = (float4*)(g_h + (size_t)gr * FIN + cg * 8);
            op[0] = make_float4(p0.x, p0.y, p1.x, p1.y);
            op[1] = make_float4(p2.x, p2.y, p3.x, p3.y);
        }
    }
}

// ---------------------------------------------------------------------------
// agg1 (pull): a1[d] = relu( di * (sum_s dinv[s]*h[s] + di*h[d]) + b1 )
// warp per node, lane holds float4 (4 cols), 4-way unrolled gather
// ---------------------------------------------------------------------------
__global__ void k_agg1(const float* __restrict__ b1, int n) {
    int node = blockIdx.x * 8 + (threadIdx.x >> 5);
    int lane = threadIdx.x & 31;
    if (node >= n) return;

    float di = g_dinv[node];
    float4 acc = ((const float4*)(g_h + (size_t)node * FIN))[lane];
    acc.x *= di; acc.y *= di; acc.z *= di; acc.w *= di;

    int beg = g_rowptr[node], end = g_rowptr[node + 1];
    int k = beg;
    for (; k + 3 < end; k += 4) {
        int s0 = g_csr[k],     s1 = g_csr[k + 1];
        int s2 = g_csr[k + 2], s3 = g_csr[k + 3];
        float w0 = g_dinv[s0], w1 = g_dinv[s1];
        float w2 = g_dinv[s2], w3 = g_dinv[s3];
        float4 v0 = ((const float4*)(g_h + (size_t)s0 * FIN))[lane];
        float4 v1 = ((const float4*)(g_h + (size_t)s1 * FIN))[lane];
        float4 v2 = ((const float4*)(g_h + (size_t)s2 * FIN))[lane];
        float4 v3 = ((const float4*)(g_h + (size_t)s3 * FIN))[lane];
        acc.x = fmaf(v0.x, w0, fmaf(v1.x, w1, fmaf(v2.x, w2, fmaf(v3.x, w3, acc.x))));
        acc.y = fmaf(v0.y, w0, fmaf(v1.y, w1, fmaf(v2.y, w2, fmaf(v3.y, w3, acc.y))));
        acc.z = fmaf(v0.z, w0, fmaf(v1.z, w1, fmaf(v2.z, w2, fmaf(v3.z, w3, acc.z))));
        acc.w = fmaf(v0.w, w0, fmaf(v1.w, w1, fmaf(v2.w, w2, fmaf(v3.w, w3, acc.w))));
    }
    for (; k < end; k++) {
        int s = g_csr[k];
        float w = g_dinv[s];
        float4 v = ((const float4*)(g_h + (size_t)s * FIN))[lane];
        acc.x = fmaf(v.x, w, acc.x);
        acc.y = fmaf(v.y, w, acc.y);
        acc.z = fmaf(v.z, w, acc.z);
        acc.w = fmaf(v.w, w, acc.w);
    }

    float4 bb = ((const float4*)b1)[lane];
    float4 z;
    z.x = fmaxf(fmaf(acc.x, di, bb.x), 0.f);
    z.y = fmaxf(fmaf(acc.y, di, bb.y), 0.f);
    z.z = fmaxf(fmaf(acc.z, di, bb.z), 0.f);
    z.w = fmaxf(fmaf(acc.w, di, bb.w), 0.f);
    ((float4*)(g_a1 + (size_t)node * FIN))[lane] = z;
}

// ---------------------------------------------------------------------------
// GEMM2: h2 = dinv * (a1 @ W2)   (N x 128 @ 128 x 40), register-tiled
// ---------------------------------------------------------------------------
__global__ void k_gemm2(const float* __restrict__ W2, int n) {
    const int KC = 32;
    __shared__ float W2s[FIN * FOUT];        // 20 KB
    __shared__ float As[128 * 36];           // 18 KB (pad 36)

    int t    = threadIdx.x;
    int r    = t >> 1;
    int half = t & 1;
    int row0 = blockIdx.x * 128;

    for (int i = t; i < FIN * FOUT / 4; i += 256)
        ((float4*)W2s)[i] = ((const float4*)W2)[i];

    float4 acc[5];
#pragma unroll
    for (int j = 0; j < 5; j++) acc[j] = make_float4(0.f, 0.f, 0.f, 0.f);

    for (int kc = 0; kc < FIN; kc += KC) {
        for (int i = t; i < 128 * (KC / 4); i += 256) {
            int rr = i >> 3;
            int k4 = i & 7;
            int gr = row0 + rr;
            float4 v = make_float4(0.f, 0.f, 0.f, 0.f);
            if (gr < n) v = ((const float4*)(g_a1 + (size_t)gr * FIN + kc))[k4];
            *(float4*)&As[rr * 36 + k4 * 4] = v;
        }
        __syncthreads();

#pragma unroll 4
        for (int kk = 0; kk < KC; kk++) {
            float av = As[r * 36 + kk];
            const float4* wp = (const float4*)(W2s + (kc + kk) * FOUT + half * 20);
            float4 w0 = wp[0];
            float4 w1 = wp[1];
            float4 w2 = wp[2];
            float4 w3 = wp[3];
            float4 w4 = wp[4];
            acc[0].x = fmaf(av, w0.x, acc[0].x); acc[0].y = fmaf(av, w0.y, acc[0].y);
            acc[0].z = fmaf(av, w0.z, acc[0].z); acc[0].w = fmaf(av, w0.w, acc[0].w);
            acc[1].x = fmaf(av, w1.x, acc[1].x); acc[1].y = fmaf(av, w1.y, acc[1].y);
            acc[1].z = fmaf(av, w1.z, acc[1].z); acc[1].w = fmaf(av, w1.w, acc[1].w);
            acc[2].x = fmaf(av, w2.x, acc[2].x); acc[2].y = fmaf(av, w2.y, acc[2].y);
            acc[2].z = fmaf(av, w2.z, acc[2].z); acc[2].w = fmaf(av, w2.w, acc[2].w);
            acc[3].x = fmaf(av, w3.x, acc[3].x); acc[3].y = fmaf(av, w3.y, acc[3].y);
            acc[3].z = fmaf(av, w3.z, acc[3].z); acc[3].w = fmaf(av, w3.w, acc[3].w);
            acc[4].x = fmaf(av, w4.x, acc[4].x); acc[4].y = fmaf(av, w4.y, acc[4].y);
            acc[4].z = fmaf(av, w4.z, acc[4].z); acc[4].w = fmaf(av, w4.w, acc[4].w);
        }
        __syncthreads();
    }

    int gr = row0 + r;
    if (gr < n) {
        float di = g_dinv[gr];
        float4* op = (float4*)(g_h2 + (size_t)gr * FOUT + half * 20);
#pragma unroll
        for (int j = 0; j < 5; j++) {
            float4 o = acc[j];
            o.x *= di; o.y *= di; o.z *= di; o.w *= di;
            op[j] = o;
        }
    }
}

// ---------------------------------------------------------------------------
// agg2 (pull): out[d] = di * (sum h2[s] + h2[d]) + b2    [h2 pre-scaled]
// ---------------------------------------------------------------------------
__global__ void k_agg2(float* __restrict__ out, const float* __restrict__ b2,
                       int n) {
    int node = blockIdx.x * 8 + (threadIdx.x >> 5);
    int lane = threadIdx.x & 31;
    if (node >= n) return;

    float di = g_dinv[node];
    const float* hp0 = g_h2 + (size_t)node * FOUT;
    float a0 = hp0[lane];
    float a1 = (lane < 8) ? hp0[32 + lane] : 0.f;

    int beg = g_rowptr[node], end = g_rowptr[node + 1];
    int k = beg;
    for (; k + 3 < end; k += 4) {
        const float* p0 = g_h2 + (size_t)g_csr[k]     * FOUT;
        const float* p1 = g_h2 + (size_t)g_csr[k + 1] * FOUT;
        const float* p2 = g_h2 + (size_t)g_csr[k + 2] * FOUT;
        const float* p3 = g_h2 + (size_t)g_csr[k + 3] * FOUT;
        a0 += (p0[lane] + p1[lane]) + (p2[lane] + p3[lane]);
        if (lane < 8)
            a1 += (p0[32 + lane] + p1[32 + lane]) + (p2[32 + lane] + p3[32 + lane]);
    }
    for (; k < end; k++) {
        const float* p = g_h2 + (size_t)g_csr[k] * FOUT;
        a0 += p[lane];
        if (lane < 8) a1 += p[32 + lane];
    }

    float* op = out + (size_t)node * FOUT;
    op[lane] = fmaf(a0, di, b2[lane]);
    if (lane < 8) op[32 + lane] = fmaf(a1, di, b2[32 + lane]);
}

// ---------------------------------------------------------------------------
extern "C" void kernel_launch(void* const* d_in, const int* in_sizes, int n_in,
                              void* d_out, int out_size) {
    const float* x   = (const float*)d_in[0];
    const void*  ei  = d_in[1];
    const float* W1  = (const float*)d_in[2];
    const float* b1  = (const float*)d_in[3];
    const float* W2  = (const float*)d_in[4];
    const float* b2  = (const float*)d_in[5];
    float*       out = (float*)d_out;

    int n = in_sizes[0] / FIN;
    if (n > NMAX) n = NMAX;
    int E = in_sizes[1] / 2;
    if (E > EMAX) E = EMAX;

    int detect_cnt = 2048;
    if (detect_cnt > E) detect_cnt = E;
    int nsb = (n + SCAN_BLK - 1) / SCAN_BLK;

    k_zero_cnt    <<<(n + 255) / 256, 256>>>(n);                 // 1 (also inits g_is64)
    k_detect      <<<(detect_cnt + 255) / 256, 256>>>((const long long*)ei, n, detect_cnt); // 2
    k_convert_hist<<<(E + 255) / 256, 256>>>(ei, E);             // 3
    k_gemm1       <<<(n + 127) / 128, 256>>>(x, W1, n);          // 4 <- profiled
    k_scanA       <<<nsb, SCAN_BLK>>>(n);                        // 5
    k_scanB       <<<1, 256>>>(nsb, n, E);                       // 6
    k_scanC       <<<(n + 255) / 256, 256>>>(n);                 // 7
    k_fill        <<<(E + 255) / 256, 256>>>(E);                 // 8
    k_agg1        <<<(n + 7) / 8, 256>>>(b1, n);                 // 9
    k_gemm2       <<<(n + 127) / 128, 256>>>(W2, n);             // 10
    k_agg2        <<<(n + 7) / 8, 256>>>(out, b2, n);            // 11
}

// round 12
// speedup vs baseline: 1.3335x; 1.1148x over previous
#include <cuda_runtime.h>
#include <cuda_fp16.h>
#include <cstdint>

#define NMAX 100000
#define EMAX 1600000
#define FIN  128
#define FOUT 40
#define SCAN_BLK 1024

typedef unsigned long long ull;

// Scratch (static __device__ — no allocations allowed)
__device__ int    g_is64;
__device__ int    g_src32 [EMAX];
__device__ int    g_dst32 [EMAX];
__device__ int    g_csr   [EMAX];        // src ids grouped by dst
__device__ int    g_degi  [NMAX];
__device__ int    g_fill  [NMAX];
__device__ int    g_rowptr[NMAX + 1];
__device__ int    g_bsum  [(NMAX + SCAN_BLK - 1) / SCAN_BLK];
__device__ int    g_boff  [(NMAX + SCAN_BLK - 1) / SCAN_BLK];
__device__ float  g_dinv[NMAX];
__device__ __half g_hh  [(size_t)NMAX * FIN];   // x @ W1 (unscaled, fp16)
__device__ float  g_a1  [(size_t)NMAX * FIN];   // relu(layer-1 out), fp32
__device__ __half g_h2h [(size_t)NMAX * FOUT];  // dinv * (a1 @ W2), fp16

// ---------------------------------------------------------------------------
// preproc
// ---------------------------------------------------------------------------
__global__ void k_zero_cnt(int n) {
    int i = blockIdx.x * blockDim.x + threadIdx.x;
    if (i < n) { g_degi[i] = 0; g_fill[i] = 0; }
    if (i == 0) g_is64 = 1;
}

__global__ void k_detect(const long long* __restrict__ ei, int n, int count) {
    int i = blockIdx.x * blockDim.x + threadIdx.x;
    if (i < count) {
        long long v = ei[i];
        if (v < 0 || v >= (long long)n) atomicAnd(&g_is64, 0);
    }
}

__global__ void k_convert_hist(const void* __restrict__ ei, int E) {
    int e = blockIdx.x * blockDim.x + threadIdx.x;
    if (e >= E) return;
    int s, d;
    if (g_is64) {
        const long long* p = (const long long*)ei;
        s = (int)p[e];
        d = (int)p[E + e];
    } else {
        const int* p = (const int*)ei;
        s = p[e];
        d = p[E + e];
    }
    g_src32[e] = s;
    g_dst32[e] = d;
    atomicAdd(&g_degi[d], 1);
}

__global__ void k_scanA(int n) {
    __shared__ int sh[SCAN_BLK];
    int tid = threadIdx.x;
    int i = blockIdx.x * SCAN_BLK + tid;
    int v = (i < n) ? g_degi[i] : 0;
    if (i < n) g_dinv[i] = rsqrtf((float)v + 1.0f);  // +1 = self loop
    sh[tid] = v;
    __syncthreads();
    for (int off = 1; off < SCAN_BLK; off <<= 1) {
        int t = (tid >= off) ? sh[tid - off] : 0;
        __syncthreads();
        sh[tid] += t;
        __syncthreads();
    }
    if (i < n) g_rowptr[i] = sh[tid] - v;  // exclusive within block
    if (tid == SCAN_BLK - 1) g_bsum[blockIdx.x] = sh[tid];
}

__global__ void k_scanB(int nblocks, int n, int E) {
    __shared__ int sh[256];
    int tid = threadIdx.x;
    int carry = 0;
    for (int base = 0; base < nblocks; base += 256) {
        int i = base + tid;
        int v = (i < nblocks) ? g_bsum[i] : 0;
        sh[tid] = v;
        __syncthreads();
        for (int off = 1; off < 256; off <<= 1) {
            int t = (tid >= off) ? sh[tid - off] : 0;
            __syncthreads();
            sh[tid] += t;
            __syncthreads();
        }
        if (i < nblocks) g_boff[i] = carry + sh[tid] - v;
        __syncthreads();
        carry += sh[255];
        __syncthreads();
    }
    if (tid == 0) g_rowptr[n] = E;
}

__global__ void k_scanC(int n) {
    int i = blockIdx.x * blockDim.x + threadIdx.x;
    if (i < n) g_rowptr[i] += g_boff[i / SCAN_BLK];
}

__global__ void k_fill(int E) {
    int e = blockIdx.x * blockDim.x + threadIdx.x;
    if (e >= E) return;
    int d = g_dst32[e];
    int pos = g_rowptr[d] + atomicAdd(&g_fill[d], 1);
    g_csr[pos] = g_src32[e];
}

// ---------------------------------------------------------------------------
// GEMM1: h = x @ W1 (unscaled), packed f32x2 FMA, conflict-free smem.
// Identical compute to R11-measured-best; epilogue stores fp16.
// ---------------------------------------------------------------------------
__global__ void __launch_bounds__(256, 2)
k_gemm1(const float* __restrict__ x, const float* __restrict__ W, int n) {
    const int KC  = 32;
    const int KC2 = KC / 2;
    __shared__ float      Ws [KC * FIN];     // 16 KB, [kk][half][cg] 16B cells
    __shared__ ulonglong2 Xs2[128 * KC2];    // 32 KB, [row][kk2 swizzled]

    int t    = threadIdx.x;
    int cg   = t & 15;         // col group: cols cg*8 .. cg*8+7
    int rg   = t >> 4;         // row group: rows rg*8 .. rg*8+7
    int row0 = blockIdx.x * 128;
    int sx   = (rg & 1) << 2;  // Xs bank swizzle for this thread

    ull acc[8][4];
#pragma unroll
    for (int r = 0; r < 8; r++)
#pragma unroll
        for (int c = 0; c < 4; c++) acc[r][c] = 0ull;

    for (int kc = 0; kc < FIN; kc += KC) {
        for (int f = t; f < KC * FIN / 4; f += 256) {
            float4 v = ((const float4*)(W + (size_t)kc * FIN))[f];
            int kk = f >> 5;
            int c4 = f & 31;
            ((float4*)Ws)[kk * 32 + (c4 & 1) * 16 + (c4 >> 1)] = v;
        }
        for (int i = t; i < 128 * KC2; i += 256) {
            int r  = i >> 4;
            int k2 = i & 15;
            int gr = row0 + r;
            float2 v = make_float2(0.f, 0.f);
            if (gr < n) v = *(const float2*)(x + (size_t)gr * FIN + kc + k2 * 2);
            ulonglong2 e;
            *(float2*)&e.x = make_float2(v.x, v.x);
            *(float2*)&e.y = make_float2(v.y, v.y);
            Xs2[r * KC2 + (k2 ^ (((r >> 3) & 1) << 2))] = e;
        }
        __syncthreads();

#pragma unroll 4
        for (int kk2 = 0; kk2 < KC2; kk2++) {
            int kidx = kk2 ^ sx;
#pragma unroll
            for (int half = 0; half < 2; half++) {
                int kk = 2 * kk2 + half;
                ulonglong2 wa = ((const ulonglong2*)Ws)[kk * 32 + cg];
                ulonglong2 wb = ((const ulonglong2*)Ws)[kk * 32 + 16 + cg];
#pragma unroll
                for (int r = 0; r < 8; r++) {
                    ulonglong2 xx = Xs2[(rg * 8 + r) * KC2 + kidx];
                    ull xv = half ? xx.y : xx.x;
                    asm("fma.rn.f32x2 %0, %1, %2, %0;" : "+l"(acc[r][0]) : "l"(xv), "l"(wa.x));
                    asm("fma.rn.f32x2 %0, %1, %2, %0;" : "+l"(acc[r][1]) : "l"(xv), "l"(wa.y));
                    asm("fma.rn.f32x2 %0, %1, %2, %0;" : "+l"(acc[r][2]) : "l"(xv), "l"(wb.x));
                    asm("fma.rn.f32x2 %0, %1, %2, %0;" : "+l"(acc[r][3]) : "l"(xv), "l"(wb.y));
                }
            }
        }
        __syncthreads();
    }

#pragma unroll
    for (int r = 0; r < 8; r++) {
        int gr = row0 + rg * 8 + r;
        if (gr < n) {
            __half2 h0 = __float22half2_rn(*(float2*)&acc[r][0]);
            __half2 h1 = __float22half2_rn(*(float2*)&acc[r][1]);
            __half2 h2 = __float22half2_rn(*(float2*)&acc[r][2]);
            __half2 h3 = __float22half2_rn(*(float2*)&acc[r][3]);
            uint4 st;
            st.x = *(unsigned*)&h0; st.y = *(unsigned*)&h1;
            st.z = *(unsigned*)&h2; st.w = *(unsigned*)&h3;
            *(uint4*)(g_hh + (size_t)gr * FIN + cg * 8) = st;
        }
    }
}

// ---------------------------------------------------------------------------
// agg1 (pull): a1[d] = relu( di * (sum_s dinv[s]*h[s] + di*h[d]) + b1 )
// warp per node, lane holds 4 cols (one uint2 = 4 halves), fp16 gathers
// ---------------------------------------------------------------------------
__device__ __forceinline__ float4 ld_h4(const __half* p, int lane) {
    uint2 u = *((const uint2*)p + lane);
    float2 lo = __half22float2(*(__half2*)&u.x);
    float2 hi = __half22float2(*(__half2*)&u.y);
    return make_float4(lo.x, lo.y, hi.x, hi.y);
}

__global__ void k_agg1(const float* __restrict__ b1, int n) {
    int node = blockIdx.x * 8 + (threadIdx.x >> 5);
    int lane = threadIdx.x & 31;
    if (node >= n) return;

    float di = g_dinv[node];
    float4 sv = ld_h4(g_hh + (size_t)node * FIN, lane);
    float4 acc = make_float4(sv.x * di, sv.y * di, sv.z * di, sv.w * di);

    int beg = g_rowptr[node], end = g_rowptr[node + 1];
    int k = beg;
    for (; k + 3 < end; k += 4) {
        int s0 = g_csr[k],     s1 = g_csr[k + 1];
        int s2 = g_csr[k + 2], s3 = g_csr[k + 3];
        float w0 = g_dinv[s0], w1 = g_dinv[s1];
        float w2 = g_dinv[s2], w3 = g_dinv[s3];
        float4 v0 = ld_h4(g_hh + (size_t)s0 * FIN, lane);
        float4 v1 = ld_h4(g_hh + (size_t)s1 * FIN, lane);
        float4 v2 = ld_h4(g_hh + (size_t)s2 * FIN, lane);
        float4 v3 = ld_h4(g_hh + (size_t)s3 * FIN, lane);
        acc.x = fmaf(v0.x, w0, fmaf(v1.x, w1, fmaf(v2.x, w2, fmaf(v3.x, w3, acc.x))));
        acc.y = fmaf(v0.y, w0, fmaf(v1.y, w1, fmaf(v2.y, w2, fmaf(v3.y, w3, acc.y))));
        acc.z = fmaf(v0.z, w0, fmaf(v1.z, w1, fmaf(v2.z, w2, fmaf(v3.z, w3, acc.z))));
        acc.w = fmaf(v0.w, w0, fmaf(v1.w, w1, fmaf(v2.w, w2, fmaf(v3.w, w3, acc.w))));
    }
    for (; k < end; k++) {
        int s = g_csr[k];
        float w = g_dinv[s];
        float4 v = ld_h4(g_hh + (size_t)s * FIN, lane);
        acc.x = fmaf(v.x, w, acc.x);
        acc.y = fmaf(v.y, w, acc.y);
        acc.z = fmaf(v.z, w, acc.z);
        acc.w = fmaf(v.w, w, acc.w);
    }

    float4 bb = ((const float4*)b1)[lane];
    float4 z;
    z.x = fmaxf(fmaf(acc.x, di, bb.x), 0.f);
    z.y = fmaxf(fmaf(acc.y, di, bb.y), 0.f);
    z.z = fmaxf(fmaf(acc.z, di, bb.z), 0.f);
    z.w = fmaxf(fmaf(acc.w, di, bb.w), 0.f);
    ((float4*)(g_a1 + (size_t)node * FIN))[lane] = z;
}

// ---------------------------------------------------------------------------
// GEMM2: h2 = dinv * (a1 @ W2), register-tiled; epilogue stores fp16
// ---------------------------------------------------------------------------
__global__ void k_gemm2(const float* __restrict__ W2, int n) {
    const int KC = 32;
    __shared__ float W2s[FIN * FOUT];        // 20 KB
    __shared__ float As[128 * 36];           // 18 KB (pad 36)

    int t    = threadIdx.x;
    int r    = t >> 1;
    int half = t & 1;
    int row0 = blockIdx.x * 128;

    for (int i = t; i < FIN * FOUT / 4; i += 256)
        ((float4*)W2s)[i] = ((const float4*)W2)[i];

    float4 acc[5];
#pragma unroll
    for (int j = 0; j < 5; j++) acc[j] = make_float4(0.f, 0.f, 0.f, 0.f);

    for (int kc = 0; kc < FIN; kc += KC) {
        for (int i = t; i < 128 * (KC / 4); i += 256) {
            int rr = i >> 3;
            int k4 = i & 7;
            int gr = row0 + rr;
            float4 v = make_float4(0.f, 0.f, 0.f, 0.f);
            if (gr < n) v = ((const float4*)(g_a1 + (size_t)gr * FIN + kc))[k4];
            *(float4*)&As[rr * 36 + k4 * 4] = v;
        }
        __syncthreads();

#pragma unroll 4
        for (int kk = 0; kk < KC; kk++) {
            float av = As[r * 36 + kk];
            const float4* wp = (const float4*)(W2s + (kc + kk) * FOUT + half * 20);
            float4 w0 = wp[0];
            float4 w1 = wp[1];
            float4 w2 = wp[2];
            float4 w3 = wp[3];
            float4 w4 = wp[4];
            acc[0].x = fmaf(av, w0.x, acc[0].x); acc[0].y = fmaf(av, w0.y, acc[0].y);
            acc[0].z = fmaf(av, w0.z, acc[0].z); acc[0].w = fmaf(av, w0.w, acc[0].w);
            acc[1].x = fmaf(av, w1.x, acc[1].x); acc[1].y = fmaf(av, w1.y, acc[1].y);
            acc[1].z = fmaf(av, w1.z, acc[1].z); acc[1].w = fmaf(av, w1.w, acc[1].w);
            acc[2].x = fmaf(av, w2.x, acc[2].x); acc[2].y = fmaf(av, w2.y, acc[2].y);
            acc[2].z = fmaf(av, w2.z, acc[2].z); acc[2].w = fmaf(av, w2.w, acc[2].w);
            acc[3].x = fmaf(av, w3.x, acc[3].x); acc[3].y = fmaf(av, w3.y, acc[3].y);
            acc[3].z = fmaf(av, w3.z, acc[3].z); acc[3].w = fmaf(av, w3.w, acc[3].w);
            acc[4].x = fmaf(av, w4.x, acc[4].x); acc[4].y = fmaf(av, w4.y, acc[4].y);
            acc[4].z = fmaf(av, w4.z, acc[4].z); acc[4].w = fmaf(av, w4.w, acc[4].w);
        }
        __syncthreads();
    }

    int gr = row0 + r;
    if (gr < n) {
        float di = g_dinv[gr];
#pragma unroll
        for (int j = 0; j < 5; j++) {
            float4 o = acc[j];
            __half2 lo = __floats2half2_rn(o.x * di, o.y * di);
            __half2 hi = __floats2half2_rn(o.z * di, o.w * di);
            uint2 st;
            st.x = *(unsigned*)&lo;
            st.y = *(unsigned*)&hi;
            *(uint2*)(g_h2h + (size_t)gr * FOUT + half * 20 + j * 4) = st;
        }
    }
}

// ---------------------------------------------------------------------------
// agg2 (pull): out[d] = di * (sum h2[s] + h2[d]) + b2    [h2 pre-scaled fp16]
// warp per node; lanes 0..19 each handle cols 2*lane, 2*lane+1 (half2 loads)
// ---------------------------------------------------------------------------
__global__ void k_agg2(float* __restrict__ out, const float* __restrict__ b2,
                       int n) {
    int node = blockIdx.x * 8 + (threadIdx.x >> 5);
    int lane = threadIdx.x & 31;
    if (node >= n || lane >= 20) return;

    float di = g_dinv[node];
    unsigned u0 = *((const unsigned*)(g_h2h + (size_t)node * FOUT) + lane);
    float2 sv = __half22float2(*(__half2*)&u0);
    float a0 = sv.x, a1 = sv.y;

    int beg = g_rowptr[node], end = g_rowptr[node + 1];
    int k = beg;
    for (; k + 3 < end; k += 4) {
        unsigned v0 = *((const unsigned*)(g_h2h + (size_t)g_csr[k]     * FOUT) + lane);
        unsigned v1 = *((const unsigned*)(g_h2h + (size_t)g_csr[k + 1] * FOUT) + lane);
        unsigned v2 = *((const unsigned*)(g_h2h + (size_t)g_csr[k + 2] * FOUT) + lane);
        unsigned v3 = *((const unsigned*)(g_h2h + (size_t)g_csr[k + 3] * FOUT) + lane);
        float2 f0 = __half22float2(*(__half2*)&v0);
        float2 f1 = __half22float2(*(__half2*)&v1);
        float2 f2 = __half22float2(*(__half2*)&v2);
        float2 f3 = __half22float2(*(__half2*)&v3);
        a0 += (f0.x + f1.x) + (f2.x + f3.x);
        a1 += (f0.y + f1.y) + (f2.y + f3.y);
    }
    for (; k < end; k++) {
        unsigned v = *((const unsigned*)(g_h2h + (size_t)g_csr[k] * FOUT) + lane);
        float2 f = __half22float2(*(__half2*)&v);
        a0 += f.x;
        a1 += f.y;
    }

    float* op = out + (size_t)node * FOUT + 2 * lane;
    op[0] = fmaf(a0, di, b2[2 * lane]);
    op[1] = fmaf(a1, di, b2[2 * lane + 1]);
}

// ---------------------------------------------------------------------------
extern "C" void kernel_launch(void* const* d_in, const int* in_sizes, int n_in,
                              void* d_out, int out_size) {
    const float* x   = (const float*)d_in[0];
    const void*  ei  = d_in[1];
    const float* W1  = (const float*)d_in[2];
    const float* b1  = (const float*)d_in[3];
    const float* W2  = (const float*)d_in[4];
    const float* b2  = (const float*)d_in[5];
    float*       out = (float*)d_out;

    int n = in_sizes[0] / FIN;
    if (n > NMAX) n = NMAX;
    int E = in_sizes[1] / 2;
    if (E > EMAX) E = EMAX;

    int detect_cnt = 2048;
    if (detect_cnt > E) detect_cnt = E;
    int nsb = (n + SCAN_BLK - 1) / SCAN_BLK;

    k_zero_cnt    <<<(n + 255) / 256, 256>>>(n);                 // 1 (also inits g_is64)
    k_detect      <<<(detect_cnt + 255) / 256, 256>>>((const long long*)ei, n, detect_cnt); // 2
    k_convert_hist<<<(E + 255) / 256, 256>>>(ei, E);             // 3
    k_gemm1       <<<(n + 127) / 128, 256>>>(x, W1, n);          // 4 <- profiled
    k_scanA       <<<nsb, SCAN_BLK>>>(n);                        // 5
    k_scanB       <<<1, 256>>>(nsb, n, E);                       // 6
    k_scanC       <<<(n + 255) / 256, 256>>>(n);                 // 7
    k_fill        <<<(E + 255) / 256, 256>>>(E);                 // 8
    k_agg1        <<<(n + 7) / 8, 256>>>(b1, n);                 // 9
    k_gemm2       <<<(n + 127) / 128, 256>>>(W2, n);             // 10
    k_agg2        <<<(n + 7) / 8, 256>>>(out, b2, n);            // 11
}